// round 1
// baseline (speedup 1.0000x reference)
#include <cuda_runtime.h>
#include <cuda_bf16.h>

// XOR-conv: out = conv_valid(x, 1 - 2*W), NCHW / OIHW, stride 1.
// x: (32,128,64,64) f32   W: (256,128,3,3) f32 (binary 0/1)
// out: (32,256,62,62) f32

#define BB   32
#define CI   128
#define HH   64
#define WWD  64
#define CO   256
#define HO   62
#define WO   62
#define CI_T 8
#define CO_T 64
#define NTHR 128

__global__ __launch_bounds__(NTHR, 4)
void xorconv_kernel(const float* __restrict__ x,
                    const float* __restrict__ w,
                    float* __restrict__ out)
{
    const int ho  = blockIdx.x;          // 0..61
    const int co0 = blockIdx.y * CO_T;   // 0,64,128,192
    const int b   = blockIdx.z;          // 0..31
    const int tid = threadIdx.x;
    const int tx  = tid & 15;            // wo group: wo = tx*4 + p
    const int ty  = tid >> 4;            // 0..7 : co = co0 + ty + 8*j

    __shared__ float sx[CI_T][3][WWD];      // 6 KB  (x rows ho..ho+2, 64 wide)
    __shared__ float sw[CO_T][CI_T * 9];    // 18 KB (sign-transformed weights)

    float acc[8][4];
#pragma unroll
    for (int j = 0; j < 8; j++)
#pragma unroll
        for (int p = 0; p < 4; p++) acc[j][p] = 0.0f;

    for (int ci0 = 0; ci0 < CI; ci0 += CI_T) {
        __syncthreads();

        // ---- stage x tile: CI_T chans x 3 rows x 64 cols, float4-coalesced ----
        // 8*3*16 = 384 float4 loads, 3 per thread
#pragma unroll
        for (int it = 0; it < 3; it++) {
            int idx = tid + it * NTHR;           // 0..383
            int seg = idx & 15;                  // 16 float4 per row
            int row = idx >> 4;                  // 0..23
            int kh  = row % 3;
            int ci  = row / 3;
            const float4 v = *(const float4*)(
                x + (((b * CI + ci0 + ci) * HH + ho + kh) * WWD + seg * 4));
            *(float4*)(&sx[ci][kh][seg * 4]) = v;
        }

        // ---- stage weights: 64 co x (8 ci * 9) floats = 18 float4 per co ----
        // 64*18 = 1152 float4, 9 per thread; transform 1-2w on the fly
#pragma unroll
        for (int it = 0; it < 9; it++) {
            int idx = tid + it * NTHR;           // 0..1151
            int seg = idx % 18;
            int col = idx / 18;                  // co local 0..63
            const float4 v = *(const float4*)(
                w + ((co0 + col) * CI + ci0) * 9 + seg * 4);
            float4 e;
            e.x = 1.0f - 2.0f * v.x;
            e.y = 1.0f - 2.0f * v.y;
            e.z = 1.0f - 2.0f * v.z;
            e.w = 1.0f - 2.0f * v.w;
            *(float4*)(&sw[col][seg * 4]) = e;
        }

        __syncthreads();

        // ---- compute: FMA-bound inner loops ----
        for (int ci = 0; ci < CI_T; ci++) {
#pragma unroll
            for (int kh = 0; kh < 3; kh++) {
                float xv[6];
#pragma unroll
                for (int c = 0; c < 6; c++)
                    xv[c] = sx[ci][kh][tx * 4 + c];
#pragma unroll
                for (int kw = 0; kw < 3; kw++) {
#pragma unroll
                    for (int j = 0; j < 8; j++) {
                        const float wj = sw[ty + 8 * j][ci * 9 + kh * 3 + kw];
#pragma unroll
                        for (int p = 0; p < 4; p++)
                            acc[j][p] = fmaf(xv[p + kw], wj, acc[j][p]);
                    }
                }
            }
        }
    }

    // ---- store: 8 co x 4 wo per thread (wo 62,63 masked) ----
#pragma unroll
    for (int j = 0; j < 8; j++) {
        const int co = co0 + ty + 8 * j;
        float* o = out + ((b * CO + co) * HO + ho) * WO;
#pragma unroll
        for (int p = 0; p < 4; p++) {
            const int wo = tx * 4 + p;
            if (wo < WO) o[wo] = acc[j][p];
        }
    }
}

extern "C" void kernel_launch(void* const* d_in, const int* in_sizes, int n_in,
                              void* d_out, int out_size)
{
    const float* x = (const float*)d_in[0];
    const float* w = (const float*)d_in[1];
    float* out = (float*)d_out;

    dim3 grid(HO, CO / CO_T, BB);   // 62 x 4 x 32 = 7936 blocks
    dim3 block(NTHR);
    xorconv_kernel<<<grid, block>>>(x, w, out);
}

// round 3
// speedup vs baseline: 6.9298x; 6.9298x over previous
#include <cuda_runtime.h>
#include <cuda_bf16.h>
#include <cstdint>
#include <cstddef>

// ---------------------------------------------------------------------------
// XOR-conv as implicit GEMM on warp-level mma.sync (bf16 HMMA) — the harness
// PTX target is sm_103 (no 'a'), so tcgen05 is unavailable; mma.sync is.
// out[b,co,ho,wo] = sum_{ci,kh,kw} (1-2W[co,ci,kh,kw]) * x[b,ci,ho+kh,wo+kw]
// x:(32,128,64,64)f32  W:(256,128,3,3)f32(binary)  out:(32,256,62,62)f32
// Exactness: eff weights are +-1 (exact bf16); x = hi + lo bf16 split, two
// bf16 GEMMs accumulated in fp32 => rel_err ~1e-5.
// ---------------------------------------------------------------------------

#define BB 32
#define CIN 128
#define HH 64
#define WWD 64
#define COUT 256
#define HOUT 62
#define WOUT 62

// Preprocessed operands (static __device__ — no dynamic alloc)
__device__ __align__(16) uint16_t g_wbuf[9 * COUT * CIN];            // bf16 (1-2W), [khw][co][ci]
__device__ __align__(16) uint32_t g_xhi[(size_t)BB * HH * WWD * 64]; // bf16x2 [b][h][w][ci/2]
__device__ __align__(16) uint32_t g_xlo[(size_t)BB * HH * WWD * 64];

// ---------------- helpers ----------------
__device__ __forceinline__ uint32_t smem_u32(const void* p) {
    uint32_t a;
    asm("{ .reg .u64 t; cvta.to.shared.u64 t, %1; cvt.u32.u64 %0, t; }" : "=r"(a) : "l"(p));
    return a;
}
__device__ __forceinline__ void cpa16(uint32_t dst, const void* src, uint32_t sz) {
    asm volatile("cp.async.cg.shared.global [%0], [%1], 16, %2;"
                 :: "r"(dst), "l"(src), "r"(sz) : "memory");
}
__device__ __forceinline__ void ldsm_x4(uint32_t* r, uint32_t a) {
    asm volatile("ldmatrix.sync.aligned.m8n8.x4.shared.b16 {%0,%1,%2,%3}, [%4];"
                 : "=r"(r[0]), "=r"(r[1]), "=r"(r[2]), "=r"(r[3]) : "r"(a));
}
#define MMA16816(c, A, b0, b1)                                                \
    asm volatile("mma.sync.aligned.m16n8k16.row.col.f32.bf16.bf16.f32 "       \
                 "{%0,%1,%2,%3}, {%4,%5,%6,%7}, {%8,%9}, {%0,%1,%2,%3};"      \
                 : "+f"((c)[0]), "+f"((c)[1]), "+f"((c)[2]), "+f"((c)[3])     \
                 : "r"((A)[0]), "r"((A)[1]), "r"((A)[2]), "r"((A)[3]),        \
                   "r"(b0), "r"(b1))

// ---------------- prep kernels ----------------
__global__ void prep_w_kernel(const float* __restrict__ w) {
    int idx = blockIdx.x * 256 + threadIdx.x;
    if (idx < 9 * COUT * CIN) {
        int khw = idx / (COUT * CIN);
        int rem = idx % (COUT * CIN);
        int co = rem >> 7, ci = rem & 127;
        int kh = khw / 3, kw = khw % 3;
        float v = 1.0f - 2.0f * w[(((size_t)co * CIN + ci) * 3 + kh) * 3 + kw];
        g_wbuf[idx] = __bfloat16_as_ushort(__float2bfloat16(v));
    }
}

__global__ void prep_x_kernel(const float* __restrict__ x) {
    __shared__ float t[CIN][67];
    const int h = blockIdx.x, b = blockIdx.y, tid = threadIdx.x;
#pragma unroll
    for (int i = 0; i < 32; i++) {
        int idx = tid + i * 256;                      // [ci][w]
        int ci = idx >> 6, w = idx & 63;
        t[ci][w] = x[(((size_t)b * CIN + ci) * HH + h) * WWD + w];
    }
    __syncthreads();
#pragma unroll
    for (int i = 0; i < 16; i++) {
        int idx = tid + i * 256;                      // [w][ci-pair]
        int w = idx >> 6, j = idx & 63;
        float a = t[2 * j][w], c = t[2 * j + 1][w];
        __nv_bfloat16 ha = __float2bfloat16(a), hc = __float2bfloat16(c);
        float la = a - __bfloat162float(ha), lc = c - __bfloat162float(hc);
        uint32_t hw2 = ((uint32_t)__bfloat16_as_ushort(hc) << 16) | __bfloat16_as_ushort(ha);
        uint32_t lw2 = ((uint32_t)__bfloat16_as_ushort(__float2bfloat16(lc)) << 16) |
                       __bfloat16_as_ushort(__float2bfloat16(la));
        size_t o = (((size_t)b * HH + h) * WWD + w) * 64 + j;
        g_xhi[o] = hw2;
        g_xlo[o] = lw2;
    }
}

// ---------------- main kernel ----------------
// smem layout (bytes from dyn base):
//   x: 2 bufs x 2 parts x (6*66*80) ;  w: 3 bufs x (128*80)
#define POS_STRIDE 80
#define XPART (6 * 66 * POS_STRIDE)       // 31680
#define XBUFSZ (2 * XPART)                // 63360
#define X_TOTAL (2 * XBUFSZ)              // 126720
#define WBUFSZ (128 * POS_STRIDE)         // 10240
#define SW_OFF X_TOTAL
#define SMEM_TOTAL (X_TOTAL + 3 * WBUFSZ) // 157440

__global__ __launch_bounds__(512, 1)
void xorconv_mma_kernel(float* __restrict__ out) {
    extern __shared__ char smraw[];
    const uint32_t SX = smem_u32(smraw);
    const uint32_t SW = SX + SW_OFF;

    const int tid = threadIdx.x;
    const int wid = tid >> 5, lid = tid & 31;
    const int wm = wid & 3;           // co sub-tile (32 rows)
    const int wn = wid >> 2;          // ho row 0..3
    const int ho0 = blockIdx.x * 4;
    const int co0 = blockIdx.y * 128;
    const int b = blockIdx.z;

    // ---- lane constants for ldmatrix addressing ----
    const int li = lid & 7, g = lid >> 3;
    // A (weights): reg order [m0-7 k0-7, m8-15 k0-7, m0-7 k8-15, m8-15 k8-15]
    const uint32_t aoff0 = (uint32_t)(wm * 32 + 0 * 16 + (g & 1) * 8 + li) * POS_STRIDE + (g >> 1) * 16;
    const uint32_t aoff1 = (uint32_t)(wm * 32 + 1 * 16 + (g & 1) * 8 + li) * POS_STRIDE + (g >> 1) * 16;
    // B (x): reg order [n0-7 k0-7, n0-7 k8-15, n8-15 k0-7, n8-15 k8-15]
    uint32_t qb[4];
#pragma unroll
    for (int j = 0; j < 4; j++)
        qb[j] = (uint32_t)(j * 16 + ((g >> 1) & 1) * 8 + li) * POS_STRIDE + (g & 1) * 16;

    float acc[2][8][4];
#pragma unroll
    for (int mi = 0; mi < 2; mi++)
#pragma unroll
        for (int ni = 0; ni < 8; ni++)
#pragma unroll
            for (int e = 0; e < 4; e++) acc[mi][ni][e] = 0.0f;

    // ---- staging lambdas ----
    auto stage_x = [&](int ci0q) {   // both parts, 32 ci, into xbuf[ci0q&1]
        const uint32_t xb = SX + (uint32_t)(ci0q & 1) * XBUFSZ;
#pragma unroll
        for (int i = 0; i < 7; i++) {
            int idx = tid + i * 512;
            if (idx < 3168) {
                int part = idx >= 1584;
                int rem = idx - part * 1584;
                int pos = rem >> 2, c4 = rem & 3;
                int hl = pos / 66, w = pos - hl * 66;
                int h = ho0 + hl;
                uint32_t sz = (h < HH && w < WWD) ? 16u : 0u;
                size_t eo = ((((size_t)b * HH + (h & 63)) * WWD + (w & 63)) * 64) + ci0q * 16 + c4 * 4;
                const char* src = (const char*)(part ? g_xlo : g_xhi) + eo * 4;
                cpa16(xb + (uint32_t)part * XPART + (uint32_t)pos * POS_STRIDE + c4 * 16, src, sz);
            }
        }
    };
    auto stage_w = [&](int ci0q, int khw, int wb) {
        if (tid < 512) {
            int co = tid >> 2, c4 = tid & 3;
            const char* src = (const char*)g_wbuf +
                (((size_t)(khw * COUT + co0 + co)) * CIN + ci0q * 32) * 2 + c4 * 16;
            cpa16(SW + (uint32_t)wb * WBUFSZ + (uint32_t)co * POS_STRIDE + c4 * 16, src, 16);
        }
    };
    auto issue_unit = [&](int u) {
        if (u >= 36) return;
        int ci0q = u / 9, khw = u % 9;
        if (khw == 0) stage_x(ci0q);
        stage_w(ci0q, khw, u % 3);
        asm volatile("cp.async.commit_group;" ::: "memory");
    };

    issue_unit(0);
    issue_unit(1);

    for (int it = 0; it < 36; it++) {
        asm volatile("cp.async.wait_group 1;" ::: "memory");
        __syncthreads();
        issue_unit(it + 2);

        const int ci0q = it / 9, khw = it % 9;
        const int kh = khw / 3, kw = khw % 3;
        const uint32_t xb = SX + (uint32_t)(ci0q & 1) * XBUFSZ;
        const uint32_t wb = SW + (uint32_t)(it % 3) * WBUFSZ;
        const uint32_t hwoff = (uint32_t)((wn + kh) * 66 + kw) * POS_STRIDE;

#pragma unroll
        for (int part = 0; part < 2; part++) {
#pragma unroll
            for (int ci16 = 0; ci16 < 2; ci16++) {
                const uint32_t xsel = xb + (uint32_t)part * XPART + ci16 * 32 + hwoff;
                const uint32_t wsel = wb + ci16 * 32;
                uint32_t a0[4], a1[4];
                ldsm_x4(a0, wsel + aoff0);
                ldsm_x4(a1, wsel + aoff1);
#pragma unroll
                for (int j = 0; j < 4; j++) {
                    uint32_t bx[4];
                    ldsm_x4(bx, xsel + qb[j]);
                    MMA16816(acc[0][2 * j], a0, bx[0], bx[1]);
                    MMA16816(acc[0][2 * j + 1], a0, bx[2], bx[3]);
                    MMA16816(acc[1][2 * j], a1, bx[0], bx[1]);
                    MMA16816(acc[1][2 * j + 1], a1, bx[2], bx[3]);
                }
            }
        }
    }

    // ---- epilogue: direct coalesced-ish float2 stores ----
    const int row = lid >> 2, qp = lid & 3;
    const int ho = ho0 + wn;
    if (ho < HOUT) {
#pragma unroll
        for (int mi = 0; mi < 2; mi++) {
            const int cor = co0 + wm * 32 + mi * 16 + row;
            float* b0p = out + (((size_t)b * COUT + cor) * HOUT + ho) * WOUT;
            float* b1p = out + (((size_t)b * COUT + cor + 8) * HOUT + ho) * WOUT;
#pragma unroll
            for (int ni = 0; ni < 8; ni++) {
                const int wo = ni * 8 + qp * 2;
                if (wo < WOUT) {   // wo even, wo+1 <= 61 guaranteed
                    *(float2*)(b0p + wo) = make_float2(acc[mi][ni][0], acc[mi][ni][1]);
                    *(float2*)(b1p + wo) = make_float2(acc[mi][ni][2], acc[mi][ni][3]);
                }
            }
        }
    }
}

// ---------------- launch ----------------
extern "C" void kernel_launch(void* const* d_in, const int* in_sizes, int n_in,
                              void* d_out, int out_size) {
    const float* x = (const float*)d_in[0];
    const float* w = (const float*)d_in[1];
    float* out = (float*)d_out;

    prep_w_kernel<<<(9 * COUT * CIN + 255) / 256, 256>>>(w);
    prep_x_kernel<<<dim3(HH, BB), 256>>>(x);

    cudaFuncSetAttribute(xorconv_mma_kernel,
                         cudaFuncAttributeMaxDynamicSharedMemorySize, SMEM_TOTAL);
    xorconv_mma_kernel<<<dim3(16, 2, BB), 512, SMEM_TOTAL>>>(out);
}

// round 5
// speedup vs baseline: 10.7837x; 1.5561x over previous
#include <cuda_runtime.h>
#include <cuda_fp16.h>
#include <cstdint>
#include <cstddef>

// ---------------------------------------------------------------------------
// XOR-conv as implicit GEMM on warp-level mma.sync, single fp16 GEMM.
// out[b,co,ho,wo] = sum_{ci,kh,kw} (1-2W[co,ci,kh,kw]) * x[b,ci,ho+kh,wo+kw]
// Weights +-1 are exact in fp16; only fp16(x) quantization contributes error:
// predicted rel_err ~2e-4 (threshold 1e-3). f32 accumulation in HMMA.
// ---------------------------------------------------------------------------

#define BB 32
#define CIN 128
#define HH 64
#define WWD 64
#define COUT 256
#define HOUT 62
#define WOUT 62

// Preprocessed operands (static __device__ — no dynamic alloc)
__device__ __align__(16) uint16_t g_wbuf[9 * COUT * CIN];            // fp16 (1-2W), [khw][co][ci]
__device__ __align__(16) uint32_t g_xh[(size_t)BB * HH * WWD * 64];  // fp16x2 [b][h][w][ci/2]

// ---------------- helpers ----------------
__device__ __forceinline__ uint32_t smem_u32(const void* p) {
    uint32_t a;
    asm("{ .reg .u64 t; cvta.to.shared.u64 t, %1; cvt.u32.u64 %0, t; }" : "=r"(a) : "l"(p));
    return a;
}
__device__ __forceinline__ void cpa16(uint32_t dst, const void* src, uint32_t sz) {
    asm volatile("cp.async.cg.shared.global [%0], [%1], 16, %2;"
                 :: "r"(dst), "l"(src), "r"(sz) : "memory");
}
__device__ __forceinline__ void ldsm_x4(uint32_t* r, uint32_t a) {
    asm volatile("ldmatrix.sync.aligned.m8n8.x4.shared.b16 {%0,%1,%2,%3}, [%4];"
                 : "=r"(r[0]), "=r"(r[1]), "=r"(r[2]), "=r"(r[3]) : "r"(a));
}
#define MMA16816(c, A, b0, b1)                                                \
    asm volatile("mma.sync.aligned.m16n8k16.row.col.f32.f16.f16.f32 "         \
                 "{%0,%1,%2,%3}, {%4,%5,%6,%7}, {%8,%9}, {%0,%1,%2,%3};"      \
                 : "+f"((c)[0]), "+f"((c)[1]), "+f"((c)[2]), "+f"((c)[3])     \
                 : "r"((A)[0]), "r"((A)[1]), "r"((A)[2]), "r"((A)[3]),        \
                   "r"(b0), "r"(b1))

// ---------------- prep kernels ----------------
__global__ void prep_w_kernel(const float* __restrict__ w) {
    int idx = blockIdx.x * 256 + threadIdx.x;
    if (idx < 9 * COUT * CIN) {
        int khw = idx / (COUT * CIN);
        int rem = idx % (COUT * CIN);
        int co = rem >> 7, ci = rem & 127;
        int kh = khw / 3, kw = khw % 3;
        float v = 1.0f - 2.0f * w[(((size_t)co * CIN + ci) * 3 + kh) * 3 + kw];
        g_wbuf[idx] = __half_as_ushort(__float2half_rn(v));
    }
}

__global__ void prep_x_kernel(const float* __restrict__ x) {
    __shared__ float t[CIN][67];
    const int h = blockIdx.x, b = blockIdx.y, tid = threadIdx.x;
#pragma unroll
    for (int i = 0; i < 32; i++) {
        int idx = tid + i * 256;                      // [ci][w]
        int ci = idx >> 6, w = idx & 63;
        t[ci][w] = x[(((size_t)b * CIN + ci) * HH + h) * WWD + w];
    }
    __syncthreads();
#pragma unroll
    for (int i = 0; i < 16; i++) {
        int idx = tid + i * 256;                      // [w][ci-pair]
        int w = idx >> 6, j = idx & 63;
        uint32_t hw2 = ((uint32_t)__half_as_ushort(__float2half_rn(t[2 * j + 1][w])) << 16) |
                       __half_as_ushort(__float2half_rn(t[2 * j][w]));
        g_xh[(((size_t)b * HH + h) * WWD + w) * 64 + j] = hw2;
    }
}

// ---------------- main kernel ----------------
// smem: x: 2 bufs x (6*66*80) ; w: 4 bufs x (128*80)
#define POS_STRIDE 80
#define XBUFSZ (6 * 66 * POS_STRIDE)      // 31680
#define X_TOTAL (2 * XBUFSZ)              // 63360
#define WBUFSZ (128 * POS_STRIDE)         // 10240
#define SW_OFF X_TOTAL
#define SMEM_TOTAL (X_TOTAL + 4 * WBUFSZ) // 104320

__global__ __launch_bounds__(512, 1)
void xorconv_mma_kernel(float* __restrict__ out) {
    extern __shared__ char smraw[];
    const uint32_t SX = smem_u32(smraw);
    const uint32_t SW = SX + SW_OFF;

    const int tid = threadIdx.x;
    const int wid = tid >> 5, lid = tid & 31;
    const int wm = wid & 3;           // co sub-tile (32 rows)
    const int wn = wid >> 2;          // ho row 0..3
    const int ho0 = blockIdx.x * 4;
    const int co0 = blockIdx.y * 128;
    const int b = blockIdx.z;

    // ---- lane constants for ldmatrix addressing ----
    const int li = lid & 7, g = lid >> 3;
    // A (weights): [m0-7 k0-7, m8-15 k0-7, m0-7 k8-15, m8-15 k8-15]
    const uint32_t aoff0 = (uint32_t)(wm * 32 + 0 * 16 + (g & 1) * 8 + li) * POS_STRIDE + (g >> 1) * 16;
    const uint32_t aoff1 = (uint32_t)(wm * 32 + 1 * 16 + (g & 1) * 8 + li) * POS_STRIDE + (g >> 1) * 16;
    // B (x): [n0-7 k0-7, n0-7 k8-15, n8-15 k0-7, n8-15 k8-15]
    uint32_t qb[4];
#pragma unroll
    for (int j = 0; j < 4; j++)
        qb[j] = (uint32_t)(j * 16 + ((g >> 1) & 1) * 8 + li) * POS_STRIDE + (g & 1) * 16;

    float acc[2][8][4];
#pragma unroll
    for (int mi = 0; mi < 2; mi++)
#pragma unroll
        for (int ni = 0; ni < 8; ni++)
#pragma unroll
            for (int e = 0; e < 4; e++) acc[mi][ni][e] = 0.0f;

    // ---- staging ----
    auto stage_x = [&](int ci0q) {   // 32 ci (16 words), into xbuf[ci0q&1]
        const uint32_t xb = SX + (uint32_t)(ci0q & 1) * XBUFSZ;
#pragma unroll
        for (int i = 0; i < 4; i++) {
            int idx = tid + i * 512;
            if (idx < 1584) {
                int pos = idx >> 2, c4 = idx & 3;
                int hl = pos / 66, w = pos - hl * 66;
                int h = ho0 + hl;
                uint32_t sz = (h < HH && w < WWD) ? 16u : 0u;
                size_t eo = ((((size_t)b * HH + (h & 63)) * WWD + (w & 63)) * 64) + ci0q * 16 + c4 * 4;
                cpa16(xb + (uint32_t)pos * POS_STRIDE + c4 * 16,
                      (const char*)g_xh + eo * 4, sz);
            }
        }
    };
    auto stage_w = [&](int ci0q, int khw, int wb) {
        int co = tid >> 2, c4 = tid & 3;
        const char* src = (const char*)g_wbuf +
            (((size_t)(khw * COUT + co0 + co)) * CIN + ci0q * 32) * 2 + c4 * 16;
        cpa16(SW + (uint32_t)wb * WBUFSZ + (uint32_t)co * POS_STRIDE + c4 * 16, src, 16);
    };
    auto issue_unit = [&](int u) {
        if (u < 36) {
            int ci0q = u / 9, khw = u % 9;
            if (khw == 0) stage_x(ci0q);
            stage_w(ci0q, khw, u & 3);
        }
        asm volatile("cp.async.commit_group;" ::: "memory");  // always: keeps group count aligned
    };

    issue_unit(0);
    issue_unit(1);
    issue_unit(2);

    for (int it = 0; it < 36; it++) {
        asm volatile("cp.async.wait_group 2;" ::: "memory");
        __syncthreads();
        issue_unit(it + 3);

        const int ci0q = it / 9, khw = it % 9;
        const int kh = khw / 3, kw = khw % 3;
        const uint32_t xb = SX + (uint32_t)(ci0q & 1) * XBUFSZ;
        const uint32_t wb = SW + (uint32_t)(it & 3) * WBUFSZ;
        const uint32_t hwoff = (uint32_t)((wn + kh) * 66 + kw) * POS_STRIDE;

#pragma unroll
        for (int ci16 = 0; ci16 < 2; ci16++) {
            const uint32_t xsel = xb + ci16 * 32 + hwoff;
            const uint32_t wsel = wb + ci16 * 32;
            uint32_t a0[4], a1[4];
            ldsm_x4(a0, wsel + aoff0);
            ldsm_x4(a1, wsel + aoff1);
#pragma unroll
            for (int j = 0; j < 4; j++) {
                uint32_t bx[4];
                ldsm_x4(bx, xsel + qb[j]);
                MMA16816(acc[0][2 * j], a0, bx[0], bx[1]);
                MMA16816(acc[0][2 * j + 1], a0, bx[2], bx[3]);
                MMA16816(acc[1][2 * j], a1, bx[0], bx[1]);
                MMA16816(acc[1][2 * j + 1], a1, bx[2], bx[3]);
            }
        }
    }

    // ---- epilogue: direct float2 stores ----
    const int row = lid >> 2, qp = lid & 3;
    const int ho = ho0 + wn;
    if (ho < HOUT) {
#pragma unroll
        for (int mi = 0; mi < 2; mi++) {
            const int cor = co0 + wm * 32 + mi * 16 + row;
            float* b0p = out + (((size_t)b * COUT + cor) * HOUT + ho) * WOUT;
            float* b1p = out + (((size_t)b * COUT + cor + 8) * HOUT + ho) * WOUT;
#pragma unroll
            for (int ni = 0; ni < 8; ni++) {
                const int wo = ni * 8 + qp * 2;
                if (wo < WOUT) {
                    *(float2*)(b0p + wo) = make_float2(acc[mi][ni][0], acc[mi][ni][1]);
                    *(float2*)(b1p + wo) = make_float2(acc[mi][ni][2], acc[mi][ni][3]);
                }
            }
        }
    }
}

// ---------------- launch ----------------
extern "C" void kernel_launch(void* const* d_in, const int* in_sizes, int n_in,
                              void* d_out, int out_size) {
    const float* x = (const float*)d_in[0];
    const float* w = (const float*)d_in[1];
    float* out = (float*)d_out;

    prep_w_kernel<<<(9 * COUT * CIN + 255) / 256, 256>>>(w);
    prep_x_kernel<<<dim3(HH, BB), 256>>>(x);

    cudaFuncSetAttribute(xorconv_mma_kernel,
                         cudaFuncAttributeMaxDynamicSharedMemorySize, SMEM_TOTAL);
    xorconv_mma_kernel<<<dim3(16, 2, BB), 512, SMEM_TOTAL>>>(out);
}